// round 17
// baseline (speedup 1.0000x reference)
#include <cuda_runtime.h>
#include <cuda_fp16.h>
#include <cstdint>

#define E_NUM   100000
#define N_NODES 40000
#define R_NUM   400
#define RH      200
#define DIN     200
#define NH      4
#define CAP     1024
#define SPLIT   16
#define KPAD    224

// ---------------- device scratch ----------------
__device__ float  g_u[NH][DIN];
__device__ float  g_v[NH][DIN];
__device__ float  g_t[NH][RH];
__device__ float4 g_s[N_NODES];
__device__ int    g_count[RH];
__device__ int    g_offs[RH + 1];
__device__ int    g_cursor[RH];
__device__ int2   g_edges[E_NUM];
__device__ float4 g_w[E_NUM];
__device__ float4 g_sc[RH];
__device__ float  g_agg[NH][RH][DIN];
__device__ float  g_relrep[RH * 400];
__device__ __align__(16) __half g_Ah[(size_t)N_NODES * KPAD];
__device__ __align__(16) __half g_Bh[400 * KPAD];

// ---------------- helpers ----------------
__device__ __forceinline__ float lrelu(float x) { return x >= 0.f ? x : 0.2f * x; }
__device__ __forceinline__ float elu(float x)   { return x > 0.f ? x : expm1f(x); }

__device__ __forceinline__ float warp_sum(float v) {
    #pragma unroll
    for (int o = 16; o; o >>= 1) v += __shfl_down_sync(0xffffffffu, v, o);
    return v;
}

__device__ __forceinline__ uint32_t smem_u32(const void* p) {
    uint32_t a;
    asm("{ .reg .u64 t; cvta.to.shared.u64 t, %1; cvt.u32.u64 %0, t; }" : "=r"(a) : "l"(p));
    return a;
}

__device__ __forceinline__ uint32_t pack_hf2(float a, float b) {
    __half2 t(__float2half_rn(a), __float2half_rn(b));
    return *(uint32_t*)&t;
}

__device__ __forceinline__ void ldm_x4(uint32_t* r, uint32_t addr) {
    asm volatile("ldmatrix.sync.aligned.m8n8.x4.shared.b16 {%0,%1,%2,%3}, [%4];"
                 : "=r"(r[0]), "=r"(r[1]), "=r"(r[2]), "=r"(r[3]) : "r"(addr));
}
__device__ __forceinline__ void ldm_x2(uint32_t* r, uint32_t addr) {
    asm volatile("ldmatrix.sync.aligned.m8n8.x2.shared.b16 {%0,%1}, [%2];"
                 : "=r"(r[0]), "=r"(r[1]) : "r"(addr));
}
__device__ __forceinline__ void mma16816(float* d, const uint32_t* a, const uint32_t* b) {
    asm volatile("mma.sync.aligned.m16n8k16.row.col.f32.f16.f16.f32 "
                 "{%0,%1,%2,%3}, {%4,%5,%6,%7}, {%8,%9}, {%0,%1,%2,%3};"
                 : "+f"(d[0]), "+f"(d[1]), "+f"(d[2]), "+f"(d[3])
                 : "r"(a[0]), "r"(a[1]), "r"(a[2]), "r"(a[3]), "r"(b[0]), "r"(b[1]));
}
__device__ __forceinline__ void cp16(uint32_t dst, const void* src, bool pred) {
    int sz = pred ? 16 : 0;
    asm volatile("cp.async.cg.shared.global [%0], [%1], 16, %2;"
                 :: "r"(dst), "l"(src), "r"(sz));
}
#define CP_COMMIT() asm volatile("cp.async.commit_group;" ::: "memory")
#define CP_WAIT1()  asm volatile("cp.async.wait_group 1;" ::: "memory")
#define CP_WAIT0()  asm volatile("cp.async.wait_group 0;" ::: "memory")

// ---------------- k_init: uv + zero(count,cursor) ----------------
__global__ void k_init(const float* __restrict__ Wsrc, const float* __restrict__ Wdst,
                       const float* __restrict__ avec) {
    int b = blockIdx.x;
    if (b < 200) {
        int w = b * 8 + (threadIdx.x >> 5);
        int lane = threadIdx.x & 31;
        int side = w / 800;
        int h = (w / 200) % 4;
        int i = w % 200;
        const float* W = (side == 0 ? Wsrc : Wdst) + h * DIN * DIN + i * DIN;
        const float* a = avec + h * 400 + side * 200;
        float acc = 0.f;
        for (int j = lane; j < DIN; j += 32) acc += W[j] * a[j];
        acc = warp_sum(acc);
        if (lane == 0) {
            if (side == 0) g_u[h][i] = acc; else g_v[h][i] = acc;
        }
    } else {
        if (threadIdx.x < RH) {
            g_count[threadIdx.x] = 0;
            g_cursor[threadIdx.x] = 0;
        }
    }
}

// ---------------- k_stcvt: s-scores + fp16 cvtA + t + hist + cvtB ----------------
__global__ void k_stcvt(const float* __restrict__ emb, const float* __restrict__ rel,
                        const int* __restrict__ etype, const float* __restrict__ Wproj) {
    __shared__ float4 su4[NH * 50];
    __shared__ int hh[RH];
    int b = blockIdx.x;
    if (b < 5000) {
        for (int i = threadIdx.x; i < NH * 50; i += 256)
            su4[i] = ((const float4*)g_u)[i];
        __syncthreads();
        int n = b * 8 + (threadIdx.x >> 5);
        int l = threadIdx.x & 31;
        const float4* row4 = (const float4*)(emb + (long)n * DIN);
        float4 x = row4[l];
        float4 u0 = su4[0 * 50 + l], u1 = su4[1 * 50 + l];
        float4 u2 = su4[2 * 50 + l], u3 = su4[3 * 50 + l];
        float a0 = x.x * u0.x + x.y * u0.y + x.z * u0.z + x.w * u0.w;
        float a1 = x.x * u1.x + x.y * u1.y + x.z * u1.z + x.w * u1.w;
        float a2 = x.x * u2.x + x.y * u2.y + x.z * u2.z + x.w * u2.w;
        float a3 = x.x * u3.x + x.y * u3.y + x.z * u3.z + x.w * u3.w;
        {
            uint2 vh;
            vh.x = pack_hf2(x.x, x.y); vh.y = pack_hf2(x.z, x.w);
            *(uint2*)&g_Ah[(long)n * KPAD + 4 * l] = vh;
        }
        if (l < 18) {
            float4 y = row4[l + 32];
            float4 v0 = su4[0 * 50 + l + 32], v1 = su4[1 * 50 + l + 32];
            float4 v2 = su4[2 * 50 + l + 32], v3 = su4[3 * 50 + l + 32];
            a0 += y.x * v0.x + y.y * v0.y + y.z * v0.z + y.w * v0.w;
            a1 += y.x * v1.x + y.y * v1.y + y.z * v1.z + y.w * v1.w;
            a2 += y.x * v2.x + y.y * v2.y + y.z * v2.z + y.w * v2.w;
            a3 += y.x * v3.x + y.y * v3.y + y.z * v3.z + y.w * v3.w;
            uint2 vh;
            vh.x = pack_hf2(y.x, y.y); vh.y = pack_hf2(y.z, y.w);
            *(uint2*)&g_Ah[(long)n * KPAD + 128 + 4 * l] = vh;
        } else if (l < 24) {
            uint2 z = make_uint2(0u, 0u);
            *(uint2*)&g_Ah[(long)n * KPAD + 128 + 4 * l] = z;
        }
        a0 = warp_sum(a0); a1 = warp_sum(a1); a2 = warp_sum(a2); a3 = warp_sum(a3);
        if (l == 0) g_s[n] = make_float4(a0, a1, a2, a3);
    } else if (b < 5100) {
        int w = (b - 5000) * 8 + (threadIdx.x >> 5);
        int lane = threadIdx.x & 31;
        int h = w / RH;
        int r = w % RH;
        const float* row = rel + (r + (h < 2 ? RH : 0)) * DIN;
        float acc = 0.f;
        for (int j = lane; j < DIN; j += 32) acc += row[j] * g_v[h][j];
        acc = warp_sum(acc);
        if (lane == 0) g_t[h][r] = acc;
    } else if (b < 5198) {
        for (int i = threadIdx.x; i < RH; i += 256) hh[i] = 0;
        __syncthreads();
        int base = (b - 5100) * 1024;
        for (int i = threadIdx.x; i < 1024; i += 256) {
            int e = base + i;
            if (e < E_NUM) atomicAdd(&hh[etype[e]], 1);
        }
        __syncthreads();
        for (int i = threadIdx.x; i < RH; i += 256)
            if (hh[i]) atomicAdd(&g_count[i], hh[i]);
    } else {
        int n = b - 5198;
        int k = threadIdx.x;
        if (k < KPAD) {
            float x = (k < 200) ? Wproj[k * 400 + n] : 0.f;
            g_Bh[n * KPAD + k] = __float2half_rn(x);
        }
    }
}

// ---------------- k_scatter: 196 blocks x 512 edges ----------------
__global__ void k_scatter(const int* __restrict__ el, const int* __restrict__ etype) {
    __shared__ int sc[256];
    __shared__ int hh[RH];
    __shared__ int bb[RH];
    int t = threadIdx.x;
    int c = (t < RH) ? g_count[t] : 0;
    sc[t] = c;
    __syncthreads();
    for (int o = 1; o < 256; o <<= 1) {
        int v = (t >= o) ? sc[t - o] : 0;
        __syncthreads();
        sc[t] += v;
        __syncthreads();
    }
    int offs_t = sc[t] - c;
    if (blockIdx.x == 0 && t < RH) {
        g_offs[t] = offs_t;
        if (t == RH - 1) g_offs[RH] = sc[t];
    }
    if (t < RH) hh[t] = 0;
    __syncthreads();
    int e0 = blockIdx.x * 512;
    int myrel[2], myrank[2];
    #pragma unroll
    for (int j = 0; j < 2; j++) {
        int e = e0 + t + j * 256;
        if (e < E_NUM) {
            myrel[j] = etype[e];
            myrank[j] = atomicAdd(&hh[myrel[j]], 1);
        } else myrel[j] = -1;
    }
    __syncthreads();
    if (t < RH) {
        int cnt = hh[t];
        if (cnt) bb[t] = offs_t + atomicAdd(&g_cursor[t], cnt);
    }
    __syncthreads();
    #pragma unroll
    for (int j = 0; j < 2; j++) {
        int e = e0 + t + j * 256;
        if (myrel[j] >= 0)
            g_edges[bb[myrel[j]] + myrank[j]] = make_int2(el[e], el[E_NUM + e]);
    }
}

// ---------------- k_w: zero g_agg + softmax stats + per-edge weights ----------------
__global__ void k_w() {
    __shared__ int2   sed[CAP];
    __shared__ float4 s_e[CAP];
    __shared__ float4 red[256];
    int r = blockIdx.x;
    int t = threadIdx.x;
    for (int i = t; i < NH * DIN; i += 256) {
        int h = i / DIN, k = i % DIN;
        g_agg[h][r][k] = 0.f;
    }
    int start = g_offs[r], end = g_offs[r + 1];
    int cnt = end - start;
    if (cnt == 0) return;
    float4 tr = make_float4(g_t[0][r], g_t[1][r], g_t[2][r], g_t[3][r]);

    for (int i = t; i < cnt && i < CAP; i += 256) sed[i] = g_edges[start + i];
    __syncthreads();

    float4 mx = make_float4(-1e30f, -1e30f, -1e30f, -1e30f);
    for (int i = t; i < cnt; i += 256) {
        int2 ed = (i < CAP) ? sed[i] : g_edges[start + i];
        float4 ss = g_s[ed.x], st = g_s[ed.y];
        float4 e;
        e.x = lrelu(ss.x + tr.x);
        e.y = lrelu(ss.y + tr.y);
        e.z = lrelu(st.z + tr.z);
        e.w = lrelu(st.w + tr.w);
        if (i < CAP) s_e[i] = e;
        mx.x = fmaxf(mx.x, e.x); mx.y = fmaxf(mx.y, e.y);
        mx.z = fmaxf(mx.z, e.z); mx.w = fmaxf(mx.w, e.w);
    }
    red[t] = mx; __syncthreads();
    for (int s = 128; s > 0; s >>= 1) {
        if (t < s) {
            float4 o = red[t + s];
            red[t].x = fmaxf(red[t].x, o.x); red[t].y = fmaxf(red[t].y, o.y);
            red[t].z = fmaxf(red[t].z, o.z); red[t].w = fmaxf(red[t].w, o.w);
        }
        __syncthreads();
    }
    float4 m = red[0]; __syncthreads();

    float4 sm = make_float4(0.f, 0.f, 0.f, 0.f);
    for (int i = t; i < cnt; i += 256) {
        float4 e;
        if (i < CAP) e = s_e[i];
        else {
            int2 ed = g_edges[start + i];
            float4 ss = g_s[ed.x], st = g_s[ed.y];
            e.x = lrelu(ss.x + tr.x); e.y = lrelu(ss.y + tr.y);
            e.z = lrelu(st.z + tr.z); e.w = lrelu(st.w + tr.w);
        }
        float4 ex;
        ex.x = expf(e.x - m.x); ex.y = expf(e.y - m.y);
        ex.z = expf(e.z - m.z); ex.w = expf(e.w - m.w);
        g_w[start + i] = ex;
        sm.x += ex.x; sm.y += ex.y; sm.z += ex.z; sm.w += ex.w;
    }
    red[t] = sm; __syncthreads();
    for (int s = 128; s > 0; s >>= 1) {
        if (t < s) {
            float4 o = red[t + s];
            red[t].x += o.x; red[t].y += o.y; red[t].z += o.z; red[t].w += o.w;
        }
        __syncthreads();
    }
    if (t == 0) {
        float4 dn = red[0];
        g_sc[r] = make_float4(1.f / (dn.x + 1e-16f), 1.f / (dn.y + 1e-16f),
                              1.f / (dn.z + 1e-16f), 1.f / (dn.w + 1e-16f));
    }
}

// ---------------- k_agg: fp16 gather, no smem staging ----------------
__global__ __launch_bounds__(128) void k_agg() {
    int r = blockIdx.x;
    int t = threadIdx.x;
    int start = g_offs[r], end = g_offs[r + 1];
    int cnt = end - start;
    if (cnt == 0) return;
    int chunk = (cnt + SPLIT - 1) / SPLIT;
    int lo = blockIdx.y * chunk;
    int hi = min(lo + chunk, cnt);
    if (lo >= hi) return;
    float4 sc = g_sc[r];
    bool act = (t < 100);
    float2 A0 = make_float2(0.f, 0.f), A1 = A0, A2 = A0, A3 = A0;
    #pragma unroll 4
    for (int j = lo; j < hi; j++) {
        float4 w = g_w[start + j];
        int2 ed  = g_edges[start + j];
        if (act) {
            __half2 hx = *(const __half2*)&g_Ah[(long)ed.x * KPAD + 2 * t];
            __half2 hy = *(const __half2*)&g_Ah[(long)ed.y * KPAD + 2 * t];
            float2 x = __half22float2(hx);
            float2 y = __half22float2(hy);
            A0.x += w.x * x.x; A0.y += w.x * x.y;
            A1.x += w.y * x.x; A1.y += w.y * x.y;
            A2.x += w.z * y.x; A2.y += w.z * y.y;
            A3.x += w.w * y.x; A3.y += w.w * y.y;
        }
    }
    if (act) {
        int d = 2 * t;
        atomicAdd(&g_agg[0][r][d],     A0.x * sc.x);
        atomicAdd(&g_agg[0][r][d + 1], A0.y * sc.x);
        atomicAdd(&g_agg[1][r][d],     A1.x * sc.y);
        atomicAdd(&g_agg[1][r][d + 1], A1.y * sc.y);
        atomicAdd(&g_agg[2][r][d],     A2.x * sc.z);
        atomicAdd(&g_agg[2][r][d + 1], A2.y * sc.z);
        atomicAdd(&g_agg[3][r][d],     A3.x * sc.w);
        atomicAdd(&g_agg[3][r][d + 1], A3.y * sc.w);
    }
}

// ---------------- k_relrep: grid (50, 2) — 4 relations x 200 cols per block ----------
__global__ __launch_bounds__(256) void k_relrep(const float* __restrict__ Wsrc) {
    __shared__ float sa2[4][2][DIN];    // [rr][0]=head y, [1]=head y+2
    int bx = blockIdx.x;                // 0..49
    int y  = blockIdx.y;                // 0..1 (head / col-half)
    int t  = threadIdx.x;
    int r0 = bx * 4;
    for (int i = t; i < 4 * 2 * DIN; i += 256) {
        int rr = i / (2 * DIN), rem = i % (2 * DIN);
        int hh2 = rem / DIN, k = rem % DIN;
        sa2[rr][hh2][k] = g_agg[y + 2 * hh2][r0 + rr][k];
    }
    __syncthreads();
    if (t >= 200) return;
    int j = t;
    const float* W1 = Wsrc + y * (DIN * DIN) + j;
    const float* W2 = Wsrc + (y + 2) * (DIN * DIN) + j;
    float d1[4] = {0.f, 0.f, 0.f, 0.f};
    float d2[4] = {0.f, 0.f, 0.f, 0.f};
    for (int k4 = 0; k4 < DIN; k4 += 4) {
        float w1a = W1[(k4 + 0) * DIN], w1b = W1[(k4 + 1) * DIN];
        float w1c = W1[(k4 + 2) * DIN], w1d = W1[(k4 + 3) * DIN];
        float w2a = W2[(k4 + 0) * DIN], w2b = W2[(k4 + 1) * DIN];
        float w2c = W2[(k4 + 2) * DIN], w2d = W2[(k4 + 3) * DIN];
        #pragma unroll
        for (int rr = 0; rr < 4; rr++) {
            float4 a1 = *(const float4*)&sa2[rr][0][k4];
            float4 a2 = *(const float4*)&sa2[rr][1][k4];
            d1[rr] += a1.x * w1a + a1.y * w1b + a1.z * w1c + a1.w * w1d;
            d2[rr] += a2.x * w2a + a2.y * w2b + a2.z * w2c + a2.w * w2d;
        }
    }
    #pragma unroll
    for (int rr = 0; rr < 4; rr++)
        g_relrep[(r0 + rr) * 400 + y * 200 + j] = elu(d1[rr]) + elu(d2[rr]);
}

// ---------------- k_relfinal: grid (25, 4) — 16 relations x 100 cols per block ----
__global__ __launch_bounds__(400) void k_relfinal(const float* __restrict__ rel,
                                                  const float* __restrict__ wrel,
                                                  float* __restrict__ out_rel) {
    __shared__ float sin_[16][600];     // 38.4 KB
    int r0 = blockIdx.x * 16;
    int c0 = blockIdx.y * 100;
    int t  = threadIdx.x;
    for (int i = t; i < 16 * 600; i += 400) {
        int rr = i / 600, k = i % 600;
        int r = r0 + rr;
        float v;
        if (k < 400) v = (r < RH) ? g_relrep[r * 400 + k] : 0.f;
        else         v = rel[r * DIN + (k - 400)];
        sin_[rr][k] = v;
    }
    __syncthreads();
    int col = c0 + (t % 100);
    int rq  = t / 100;                  // 0..3
    float acc[4] = {0.f, 0.f, 0.f, 0.f};
    for (int k = 0; k < 600; k += 2) {
        float wa = wrel[k * 400 + col];
        float wb = wrel[(k + 1) * 400 + col];
        #pragma unroll
        for (int i = 0; i < 4; i++) {
            int rr = rq * 4 + i;
            acc[i] += sin_[rr][k] * wa + sin_[rr][k + 1] * wb;
        }
    }
    #pragma unroll
    for (int i = 0; i < 4; i++)
        out_rel[(r0 + rq * 4 + i) * 400 + col] = acc[i];
}

// ---------------- k_entmm: cp.async double-buffered plain-fp16 HMMA GEMM ----------------
#define BM 128
#define BN 80
#define KC 32
#define AST 40
#define BST 40
#define A_TILE_B (BM * AST * 2)
#define B_TILE_B (BN * BST * 2)
#define STAGE_B  (A_TILE_B + B_TILE_B)
#define NCHUNK   7

__global__ __launch_bounds__(256) void k_entmm(float* __restrict__ C) {
    __shared__ __align__(16) unsigned char smbuf[2 * STAGE_B];
    const int tid = threadIdx.x;
    const int warp = tid >> 5, lane = tid & 31;
    const int wm = warp & 3;
    const int wn = warp >> 2;
    const int bm = blockIdx.y * BM;
    const int bn = blockIdx.x * BN;

    float acc[2][5][4];
    #pragma unroll
    for (int i = 0; i < 2; i++)
        #pragma unroll
        for (int j = 0; j < 5; j++)
            #pragma unroll
            for (int c = 0; c < 4; c++) acc[i][j][c] = 0.f;

    const uint32_t smem0 = smem_u32(smbuf);
    const int a_row = wm * 32 + (lane & 15);
    const int a_koff = (lane >> 4) * 8;
    const int b_row = wn * 40 + (lane & 7);
    const int b_koff = ((lane >> 3) & 1) * 8;

    auto load_chunk = [&](int kc, int s) {
        uint32_t base = smem0 + s * STAGE_B;
        uint32_t sAh = base;
        uint32_t sBh = base + A_TILE_B;
        #pragma unroll
        for (int i = 0; i < 2; i++) {
            int idx = tid + i * 256;
            int row = idx >> 2, j = idx & 3;
            int grow = bm + row;
            cp16(sAh + (row * AST + j * 8) * 2, g_Ah + (long)grow * KPAD + kc + j * 8,
                 grow < N_NODES);
        }
        for (int idx = tid; idx < 320; idx += 256) {
            int row = idx >> 2, j = idx & 3;
            cp16(sBh + (row * BST + j * 8) * 2,
                 g_Bh + (long)(bn + row) * KPAD + kc + j * 8, true);
        }
    };

    load_chunk(0, 0);
    CP_COMMIT();

    int cur = 0;
    #pragma unroll 1
    for (int ci = 0; ci < NCHUNK; ci++) {
        if (ci + 1 < NCHUNK) {
            load_chunk((ci + 1) * KC, cur ^ 1);
            CP_COMMIT();
            CP_WAIT1();
        } else {
            CP_WAIT0();
        }
        __syncthreads();

        uint32_t base = smem0 + cur * STAGE_B;
        uint32_t sAh32 = base;
        uint32_t sBh32 = base + A_TILE_B;

        int nks = (ci == NCHUNK - 1) ? 1 : 2;
        for (int ks = 0; ks < nks; ks++) {
            int k0 = ks * 16;
            uint32_t afh[2][4], bfh[5][2];
            #pragma unroll
            for (int mf = 0; mf < 2; mf++)
                ldm_x4(afh[mf], sAh32 + ((a_row + mf * 16) * AST + k0 + a_koff) * 2);
            #pragma unroll
            for (int nf = 0; nf < 5; nf++)
                ldm_x2(bfh[nf], sBh32 + ((b_row + nf * 8) * BST + k0 + b_koff) * 2);
            #pragma unroll
            for (int mf = 0; mf < 2; mf++)
                #pragma unroll
                for (int nf = 0; nf < 5; nf++)
                    mma16816(acc[mf][nf], afh[mf], bfh[nf]);
        }
        __syncthreads();
        cur ^= 1;
    }

    const int m_base = bm + wm * 32 + (lane >> 2);
    const int n_base = bn + wn * 40 + (lane & 3) * 2;
    #pragma unroll
    for (int mf = 0; mf < 2; mf++) {
        #pragma unroll
        for (int nf = 0; nf < 5; nf++) {
            int n = n_base + nf * 8;
            int m0 = m_base + mf * 16;
            if (m0 < N_NODES)
                *(float2*)&C[(long)m0 * 400 + n] = make_float2(acc[mf][nf][0], acc[mf][nf][1]);
            if (m0 + 8 < N_NODES)
                *(float2*)&C[(long)(m0 + 8) * 400 + n] = make_float2(acc[mf][nf][2], acc[mf][nf][3]);
        }
    }
}

// ---------------- launch ----------------
extern "C" void kernel_launch(void* const* d_in, const int* in_sizes, int n_in,
                              void* d_out, int out_size) {
    const int*   el    = (const int*)d_in[0];
    const int*   et    = (const int*)d_in[1];
    const float* emb   = (const float*)d_in[2];
    const float* rel   = (const float*)d_in[3];
    const float* Wsrc  = (const float*)d_in[4];
    const float* Wdst  = (const float*)d_in[5];
    const float* avec  = (const float*)d_in[6];
    const float* wrel  = (const float*)d_in[7];
    const float* Wproj = (const float*)d_in[8];
    float* out     = (float*)d_out;
    float* out_ent = out;
    float* out_rel = out + (long)N_NODES * 400;

    cudaStream_t s2;
    cudaEvent_t ev_fork, ev_join;
    cudaStreamCreateWithFlags(&s2, cudaStreamNonBlocking);
    cudaEventCreateWithFlags(&ev_fork, cudaEventDisableTiming);
    cudaEventCreateWithFlags(&ev_join, cudaEventDisableTiming);

    // edge chain (main stream)
    k_init<<<201, 256>>>(Wsrc, Wdst, avec);
    k_stcvt<<<5598, 256>>>(emb, rel, et, Wproj);
    cudaEventRecord(ev_fork, 0);               // g_Ah/g_Bh ready after k_stcvt
    k_scatter<<<196, 256>>>(el, et);
    k_w<<<RH, 256>>>();
    k_agg<<<dim3(RH, SPLIT), 128>>>();
    k_relrep<<<dim3(50, 2), 256>>>(Wsrc);
    k_relfinal<<<dim3(25, 4), 400>>>(rel, wrel, out_rel);

    // GEMM chain on side stream (overlaps tail of edge chain)
    cudaStreamWaitEvent(s2, ev_fork, 0);
    k_entmm<<<dim3(5, 313), 256, 0, s2>>>(out_ent);
    cudaEventRecord(ev_join, s2);
    cudaStreamWaitEvent(0, ev_join, 0);
}